// round 13
// baseline (speedup 1.0000x reference)
#include <cuda_runtime.h>
#include <math.h>

// Problem constants
#define HH     8192
#define IDIM   4096
#define ODIM   4096
#define NTOT   (HH + ODIM)      // 12288
#define NSTEPS 100
#define RPB    4                // rows per GEMV work group
#define IZB    256              // neurons per izhi work group

// Scratch (no allocations allowed)
__device__ __align__(128) float g_Ihid[HH];      // compress(W1 @ v_input)
__device__ __align__(128) float g_Iout[ODIM];    // compress(W2 @ I_hidden)
__device__ __align__(128) float g_total_hid[HH]; // I_hidden - Wfb @ I_output

// Work-stealing counters (one per phase) + grid barrier state.
__device__ unsigned g_ctr[4];
__device__ unsigned g_bar_cnt = 0;
__device__ volatile unsigned g_bar_gen = 0;

__device__ __forceinline__ void grid_barrier() {
    __syncthreads();
    if (threadIdx.x == 0) {
        unsigned gen = g_bar_gen;           // read phase BEFORE arriving
        __threadfence();                    // publish this block's writes
        if (atomicAdd(&g_bar_cnt, 1u) == gridDim.x - 1u) {
            g_bar_cnt = 0;
            __threadfence();
            g_bar_gen = gen + 1u;           // release
        } else {
            while (g_bar_gen == gen) { }
        }
    }
    __syncthreads();
}

__device__ __forceinline__ float compress_fn(float x, float gain) {
    float s = (x > 0.0f) ? 1.0f : ((x < 0.0f) ? -1.0f : 0.0f);
    return s * log1pf(gain * fabsf(x) + 1e-6f);
}

// 4-row dot: 256 threads, thread t handles idx = k*256+t, elements .x.y.z.w.
// Per-row FMA ordering identical to all passing kernels.
template <int NCOLS>
__device__ __forceinline__ void rows4_dot(const float* __restrict__ W,
                                          const float* __restrict__ x,
                                          int row0,
                                          float& a0, float& a1, float& a2, float& a3) {
    const float4* xv = reinterpret_cast<const float4*>(x);
    const float4* w0 = reinterpret_cast<const float4*>(W + (size_t)(row0 + 0) * NCOLS);
    const float4* w1 = reinterpret_cast<const float4*>(W + (size_t)(row0 + 1) * NCOLS);
    const float4* w2 = reinterpret_cast<const float4*>(W + (size_t)(row0 + 2) * NCOLS);
    const float4* w3 = reinterpret_cast<const float4*>(W + (size_t)(row0 + 3) * NCOLS);
    constexpr int PER = NCOLS / 4 / 256;
    a0 = a1 = a2 = a3 = 0.0f;
    #pragma unroll
    for (int k = 0; k < PER; ++k) {
        int idx = k * 256 + threadIdx.x;
        float4 xx = xv[idx];
        float4 r0 = w0[idx];
        float4 r1 = w1[idx];
        float4 r2 = w2[idx];
        float4 r3 = w3[idx];
        a0 = fmaf(r0.x, xx.x, a0); a0 = fmaf(r0.y, xx.y, a0);
        a0 = fmaf(r0.z, xx.z, a0); a0 = fmaf(r0.w, xx.w, a0);
        a1 = fmaf(r1.x, xx.x, a1); a1 = fmaf(r1.y, xx.y, a1);
        a1 = fmaf(r1.z, xx.z, a1); a1 = fmaf(r1.w, xx.w, a1);
        a2 = fmaf(r2.x, xx.x, a2); a2 = fmaf(r2.y, xx.y, a2);
        a2 = fmaf(r2.z, xx.z, a2); a2 = fmaf(r2.w, xx.w, a2);
        a3 = fmaf(r3.x, xx.x, a3); a3 = fmaf(r3.y, xx.y, a3);
        a3 = fmaf(r3.z, xx.z, a3); a3 = fmaf(r3.w, xx.w, a3);
    }
}

// Block reduce of 4 sums, 256 threads. Same xor tree as passing kernels.
__device__ __forceinline__ void block_reduce4(float& a0, float& a1, float& a2, float& a3) {
    __shared__ float s[8][4];
    __syncthreads();
    #pragma unroll
    for (int o = 16; o > 0; o >>= 1) {
        a0 += __shfl_xor_sync(0xffffffffu, a0, o);
        a1 += __shfl_xor_sync(0xffffffffu, a1, o);
        a2 += __shfl_xor_sync(0xffffffffu, a2, o);
        a3 += __shfl_xor_sync(0xffffffffu, a3, o);
    }
    if ((threadIdx.x & 31) == 0) {
        int w = threadIdx.x >> 5;
        s[w][0] = a0; s[w][1] = a1; s[w][2] = a2; s[w][3] = a3;
    }
    __syncthreads();
    if (threadIdx.x < 32) {
        bool in = threadIdx.x < 8;
        a0 = in ? s[threadIdx.x][0] : 0.0f;
        a1 = in ? s[threadIdx.x][1] : 0.0f;
        a2 = in ? s[threadIdx.x][2] : 0.0f;
        a3 = in ? s[threadIdx.x][3] : 0.0f;
        #pragma unroll
        for (int o = 4; o > 0; o >>= 1) {
            a0 += __shfl_xor_sync(0xffffffffu, a0, o);
            a1 += __shfl_xor_sync(0xffffffffu, a1, o);
            a2 += __shfl_xor_sync(0xffffffffu, a2, o);
            a3 += __shfl_xor_sync(0xffffffffu, a3, o);
        }
    }
}

// 100-step Izhikevich trajectory for one neuron. Consecutive threads handle
// consecutive neurons -> fully coalesced 1KB stores per step per block.
// Output layout: out[0]=loss, v at out[1 + t*NTOT + n], u after all v.
__device__ __forceinline__ void izhi_run(int n, float Iin, float* __restrict__ out) {
    float* vp = out + 1 + n;
    float* up = out + 1 + (size_t)NSTEPS * NTOT + n;
    float v = -65.0f;
    float u = 0.2f * -65.0f;   // -13
    *vp = v; *up = u;
    #pragma unroll 4
    for (int t = 1; t < NSTEPS; ++t) {
        vp += NTOT; up += NTOT;
        float vn = v + (0.04f * v * v + 5.0f * v + 0.14f - u + Iin);
        float un = u + 0.02f * (0.2f * v - u);
        bool sp = (vn >= 30.0f);
        v = sp ? -65.0f : vn;
        u = sp ? (un + 8.0f) : un;
        *vp = v; *up = u;
    }
}

// Steal next work id from counter c. Uniform across block.
__device__ __forceinline__ int steal(int c) {
    __shared__ int sg;
    __syncthreads();                 // protect sg from previous iteration
    if (threadIdx.x == 0) sg = (int)atomicAdd(&g_ctr[c], 1u);
    __syncthreads();
    return sg;
}

// One persistent kernel. Grid = SMs * occupancy (all blocks co-resident).
__global__ __launch_bounds__(256) void k_fused(
    const float* __restrict__ vin,   const float* __restrict__ target,
    const float* __restrict__ W1,    const float* __restrict__ W2,
    const float* __restrict__ Wfb,   const float* __restrict__ gain1,
    const float* __restrict__ gain2, float* __restrict__ out)
{
    // ---- Reset steal counters, then sync ----
    if (blockIdx.x == 0 && threadIdx.x < 4) g_ctr[threadIdx.x] = 0u;
    grid_barrier();

    // ---- Phase 1: g_Ihid = compress(W1 @ v_input, gain1), 2048 groups ----
    for (;;) {
        int g = steal(0);
        if (g >= HH / RPB) break;
        int row0 = g * RPB;
        float a0, a1, a2, a3;
        rows4_dot<IDIM>(W1, vin, row0, a0, a1, a2, a3);
        block_reduce4(a0, a1, a2, a3);
        if (threadIdx.x == 0) {
            float gn = gain1[0];
            g_Ihid[row0 + 0] = compress_fn(a0, gn);
            g_Ihid[row0 + 1] = compress_fn(a1, gn);
            g_Ihid[row0 + 2] = compress_fn(a2, gn);
            g_Ihid[row0 + 3] = compress_fn(a3, gn);
        }
    }
    grid_barrier();

    // ---- Phase 2: g_Iout = compress(W2 @ g_Ihid, gain2), 1024 groups ----
    for (;;) {
        int g = steal(1);
        if (g >= ODIM / RPB) break;
        int row0 = g * RPB;
        float a0, a1, a2, a3;
        rows4_dot<HH>(W2, g_Ihid, row0, a0, a1, a2, a3);
        block_reduce4(a0, a1, a2, a3);
        if (threadIdx.x == 0) {
            float gn = gain2[0];
            g_Iout[row0 + 0] = compress_fn(a0, gn);
            g_Iout[row0 + 1] = compress_fn(a1, gn);
            g_Iout[row0 + 2] = compress_fn(a2, gn);
            g_Iout[row0 + 3] = compress_fn(a3, gn);
        }
    }
    grid_barrier();

    // ---- Phase 3: output-neuron izhi + loss FIRST (hidden under the Wfb
    //      stream run by the other ~740 blocks), then Wfb row groups ----
    const int NG_OIZ  = ODIM / IZB;          // 16 izhi groups
    const int ID_LOSS = NG_OIZ;              // 1 loss group
    const int W_BASE  = NG_OIZ + 1;          // Wfb groups start here
    const int NG3     = W_BASE + HH / RPB;   // total
    for (;;) {
        int g = steal(2);
        if (g >= NG3) break;
        if (g < NG_OIZ) {
            int n = g * IZB + threadIdx.x;
            izhi_run(HH + n, g_Iout[n], out);
        } else if (g == ID_LOSS) {
            float acc = 0.0f;
            for (int i = threadIdx.x; i < ODIM; i += 256) {
                float d = g_Iout[i] - target[i];
                acc = fmaf(d, d, acc);
            }
            __shared__ float ls[8];
            #pragma unroll
            for (int o = 16; o > 0; o >>= 1)
                acc += __shfl_xor_sync(0xffffffffu, acc, o);
            if ((threadIdx.x & 31) == 0) ls[threadIdx.x >> 5] = acc;
            __syncthreads();
            if (threadIdx.x < 32) {
                acc = (threadIdx.x < 8) ? ls[threadIdx.x] : 0.0f;
                #pragma unroll
                for (int o = 4; o > 0; o >>= 1)
                    acc += __shfl_xor_sync(0xffffffffu, acc, o);
                if (threadIdx.x == 0)
                    out[0] = acc / (float)ODIM;
            }
        } else {
            int row0 = (g - W_BASE) * RPB;
            float a0, a1, a2, a3;
            rows4_dot<ODIM>(Wfb, g_Iout, row0, a0, a1, a2, a3);
            block_reduce4(a0, a1, a2, a3);
            if (threadIdx.x == 0) {
                g_total_hid[row0 + 0] = g_Ihid[row0 + 0] - a0;
                g_total_hid[row0 + 1] = g_Ihid[row0 + 1] - a1;
                g_total_hid[row0 + 2] = g_Ihid[row0 + 2] - a2;
                g_total_hid[row0 + 3] = g_Ihid[row0 + 3] - a3;
            }
        }
    }
    grid_barrier();

    // ---- Phase 4: hidden-neuron izhi, 256 neurons/block, 32 groups ----
    for (;;) {
        int g = steal(3);
        if (g >= HH / IZB) break;
        int n = g * IZB + threadIdx.x;
        izhi_run(n, g_total_hid[n], out);
    }
}

extern "C" void kernel_launch(void* const* d_in, const int* in_sizes, int n_in,
                              void* d_out, int out_size) {
    // metadata order: v_input, target_output, W1, W2, W_feedback, gain1, gain2
    const float* v_input = (const float*)d_in[0];
    const float* target  = (const float*)d_in[1];
    const float* W1      = (const float*)d_in[2];
    const float* W2      = (const float*)d_in[3];
    const float* Wfb     = (const float*)d_in[4];
    const float* gain1   = (const float*)d_in[5];
    const float* gain2   = (const float*)d_in[6];
    float* out = (float*)d_out;

    // Grid sized to guaranteed co-residency (spin barrier is deadlock-free).
    int dev = 0;
    cudaGetDevice(&dev);
    int sm = 0;
    cudaDeviceGetAttribute(&sm, cudaDevAttrMultiProcessorCount, dev);
    int occ = 0;
    cudaOccupancyMaxActiveBlocksPerMultiprocessor(&occ, k_fused, 256, 0);
    if (occ < 1) occ = 1;
    if (sm < 1) sm = 1;
    int grid = sm * occ;

    k_fused<<<grid, 256>>>(v_input, target, W1, W2, Wfb, gain1, gain2, out);
    (void)in_sizes; (void)n_in; (void)out_size;
}

// round 14
// speedup vs baseline: 1.2173x; 1.2173x over previous
#include <cuda_runtime.h>
#include <math.h>

// Problem constants
#define HH     8192
#define IDIM   4096
#define ODIM   4096
#define NTOT   (HH + ODIM)      // 12288
#define NSTEPS 100
#define MAXROWS 64              // max rows any block can own (grid >= 152)

// Scratch (no allocations allowed)
__device__ __align__(128) float g_Ihid[HH];   // compress(W1 @ v_input)
__device__ __align__(128) float g_Iout[ODIM]; // compress(W2 @ I_hidden)

// Grid barrier state (sense-reversal; safe across graph replays).
__device__ unsigned g_bar_cnt = 0;
__device__ volatile unsigned g_bar_gen = 0;

__device__ __forceinline__ void grid_barrier() {
    __syncthreads();
    if (threadIdx.x == 0) {
        unsigned gen = g_bar_gen;           // read phase BEFORE arriving
        __threadfence();                    // publish this block's writes
        if (atomicAdd(&g_bar_cnt, 1u) == gridDim.x - 1u) {
            g_bar_cnt = 0;
            __threadfence();
            g_bar_gen = gen + 1u;           // release
        } else {
            while (g_bar_gen == gen) { }
        }
    }
    __syncthreads();
}

__device__ __forceinline__ float compress_fn(float x, float gain) {
    float s = (x > 0.0f) ? 1.0f : ((x < 0.0f) ? -1.0f : 0.0f);
    return s * log1pf(gain * fabsf(x) + 1e-6f);
}

__device__ __forceinline__ int range_pt(int b, int G, int R) {
    return (int)(((long long)b * R) / G);
}

// 4-row dot: 256 threads, thread t handles idx = k*256+t, elements .x.y.z.w.
// Per-row FMA ordering identical to all passing kernels.
template <int NCOLS>
__device__ __forceinline__ void rows4_dot(const float* __restrict__ W,
                                          const float* __restrict__ x,
                                          int row0,
                                          float& a0, float& a1, float& a2, float& a3) {
    const float4* xv = reinterpret_cast<const float4*>(x);
    const float4* w0 = reinterpret_cast<const float4*>(W + (size_t)(row0 + 0) * NCOLS);
    const float4* w1 = reinterpret_cast<const float4*>(W + (size_t)(row0 + 1) * NCOLS);
    const float4* w2 = reinterpret_cast<const float4*>(W + (size_t)(row0 + 2) * NCOLS);
    const float4* w3 = reinterpret_cast<const float4*>(W + (size_t)(row0 + 3) * NCOLS);
    constexpr int PER = NCOLS / 4 / 256;
    a0 = a1 = a2 = a3 = 0.0f;
    #pragma unroll
    for (int k = 0; k < PER; ++k) {
        int idx = k * 256 + threadIdx.x;
        float4 xx = xv[idx];
        float4 r0 = w0[idx];
        float4 r1 = w1[idx];
        float4 r2 = w2[idx];
        float4 r3 = w3[idx];
        a0 = fmaf(r0.x, xx.x, a0); a0 = fmaf(r0.y, xx.y, a0);
        a0 = fmaf(r0.z, xx.z, a0); a0 = fmaf(r0.w, xx.w, a0);
        a1 = fmaf(r1.x, xx.x, a1); a1 = fmaf(r1.y, xx.y, a1);
        a1 = fmaf(r1.z, xx.z, a1); a1 = fmaf(r1.w, xx.w, a1);
        a2 = fmaf(r2.x, xx.x, a2); a2 = fmaf(r2.y, xx.y, a2);
        a2 = fmaf(r2.z, xx.z, a2); a2 = fmaf(r2.w, xx.w, a2);
        a3 = fmaf(r3.x, xx.x, a3); a3 = fmaf(r3.y, xx.y, a3);
        a3 = fmaf(r3.z, xx.z, a3); a3 = fmaf(r3.w, xx.w, a3);
    }
}

// Single-row dot, same per-thread/index ordering.
template <int NCOLS>
__device__ __forceinline__ float row1_dot(const float* __restrict__ W,
                                          const float* __restrict__ x, int row) {
    const float4* xv = reinterpret_cast<const float4*>(x);
    const float4* wr = reinterpret_cast<const float4*>(W + (size_t)row * NCOLS);
    constexpr int PER = NCOLS / 4 / 256;
    float a = 0.0f;
    #pragma unroll
    for (int k = 0; k < PER; ++k) {
        int idx = k * 256 + threadIdx.x;
        float4 xx = xv[idx];
        float4 ww = wr[idx];
        a = fmaf(ww.x, xx.x, a); a = fmaf(ww.y, xx.y, a);
        a = fmaf(ww.z, xx.z, a); a = fmaf(ww.w, xx.w, a);
    }
    return a;
}

// Block reduce of 4 sums, 256 threads. Same xor tree as passing kernels.
__device__ __forceinline__ void block_reduce4(float& a0, float& a1, float& a2, float& a3) {
    __shared__ float s[8][4];
    __syncthreads();
    #pragma unroll
    for (int o = 16; o > 0; o >>= 1) {
        a0 += __shfl_xor_sync(0xffffffffu, a0, o);
        a1 += __shfl_xor_sync(0xffffffffu, a1, o);
        a2 += __shfl_xor_sync(0xffffffffu, a2, o);
        a3 += __shfl_xor_sync(0xffffffffu, a3, o);
    }
    if ((threadIdx.x & 31) == 0) {
        int w = threadIdx.x >> 5;
        s[w][0] = a0; s[w][1] = a1; s[w][2] = a2; s[w][3] = a3;
    }
    __syncthreads();
    if (threadIdx.x < 32) {
        bool in = threadIdx.x < 8;
        a0 = in ? s[threadIdx.x][0] : 0.0f;
        a1 = in ? s[threadIdx.x][1] : 0.0f;
        a2 = in ? s[threadIdx.x][2] : 0.0f;
        a3 = in ? s[threadIdx.x][3] : 0.0f;
        #pragma unroll
        for (int o = 4; o > 0; o >>= 1) {
            a0 += __shfl_xor_sync(0xffffffffu, a0, o);
            a1 += __shfl_xor_sync(0xffffffffu, a1, o);
            a2 += __shfl_xor_sync(0xffffffffu, a2, o);
            a3 += __shfl_xor_sync(0xffffffffu, a3, o);
        }
    }
}

// Block reduce of 1 sum (identical to R7's proven tree).
__device__ __forceinline__ float block_reduce1(float val) {
    __shared__ float s1[8];
    __syncthreads();
    #pragma unroll
    for (int o = 16; o > 0; o >>= 1)
        val += __shfl_xor_sync(0xffffffffu, val, o);
    if ((threadIdx.x & 31) == 0) s1[threadIdx.x >> 5] = val;
    __syncthreads();
    if (threadIdx.x < 32) {
        val = (threadIdx.x < 8) ? s1[threadIdx.x] : 0.0f;
        #pragma unroll
        for (int o = 4; o > 0; o >>= 1)
            val += __shfl_xor_sync(0xffffffffu, val, o);
    }
    return val;
}

// 100-step Izhikevich trajectory for one neuron.
// Output layout: out[0]=loss, v at out[1 + t*NTOT + n], u after all v.
__device__ __forceinline__ void izhi_run(int n, float Iin, float* __restrict__ out) {
    float* vp = out + 1 + n;
    float* up = out + 1 + (size_t)NSTEPS * NTOT + n;
    float v = -65.0f;
    float u = 0.2f * -65.0f;   // -13
    *vp = v; *up = u;
    #pragma unroll 4
    for (int t = 1; t < NSTEPS; ++t) {
        vp += NTOT; up += NTOT;
        float vn = v + (0.04f * v * v + 5.0f * v + 0.14f - u + Iin);
        float un = u + 0.02f * (0.2f * v - u);
        bool sp = (vn >= 30.0f);
        v = sp ? -65.0f : vn;
        u = sp ? (un + 8.0f) : un;
        *vp = v; *up = u;
    }
}

// Persistent kernel, all blocks co-resident. Static contiguous row ranges.
__global__ void __launch_bounds__(256, 4) k_fused(
    const float* __restrict__ vin,   const float* __restrict__ target,
    const float* __restrict__ W1,    const float* __restrict__ W2,
    const float* __restrict__ Wfb,   const float* __restrict__ gain1,
    const float* __restrict__ gain2, float* __restrict__ out)
{
    const int G = gridDim.x;
    const int b = blockIdx.x;

    // ---- Phase 1: g_Ihid = compress(W1 @ v_input, gain1) ----
    {
        int r0 = range_pt(b, G, HH), r1 = range_pt(b + 1, G, HH);
        int r = r0;
        for (; r + 4 <= r1; r += 4) {
            float a0, a1, a2, a3;
            rows4_dot<IDIM>(W1, vin, r, a0, a1, a2, a3);
            block_reduce4(a0, a1, a2, a3);
            if (threadIdx.x == 0) {
                float gn = gain1[0];
                g_Ihid[r + 0] = compress_fn(a0, gn);
                g_Ihid[r + 1] = compress_fn(a1, gn);
                g_Ihid[r + 2] = compress_fn(a2, gn);
                g_Ihid[r + 3] = compress_fn(a3, gn);
            }
        }
        for (; r < r1; ++r) {
            float a = row1_dot<IDIM>(W1, vin, r);
            a = block_reduce1(a);
            if (threadIdx.x == 0)
                g_Ihid[r] = compress_fn(a, gain1[0]);
        }
    }
    grid_barrier();

    // ---- Phase 2: g_Iout = compress(W2 @ g_Ihid, gain2) ----
    {
        int r0 = range_pt(b, G, ODIM), r1 = range_pt(b + 1, G, ODIM);
        int r = r0;
        for (; r + 4 <= r1; r += 4) {
            float a0, a1, a2, a3;
            rows4_dot<HH>(W2, g_Ihid, r, a0, a1, a2, a3);
            block_reduce4(a0, a1, a2, a3);
            if (threadIdx.x == 0) {
                float gn = gain2[0];
                g_Iout[r + 0] = compress_fn(a0, gn);
                g_Iout[r + 1] = compress_fn(a1, gn);
                g_Iout[r + 2] = compress_fn(a2, gn);
                g_Iout[r + 3] = compress_fn(a3, gn);
            }
        }
        for (; r < r1; ++r) {
            float a = row1_dot<HH>(W2, g_Ihid, r);
            a = block_reduce1(a);
            if (threadIdx.x == 0)
                g_Iout[r] = compress_fn(a, gain2[0]);
        }
    }
    grid_barrier();

    // ---- Phase 3: total_hidden = g_Ihid - Wfb @ g_Iout (currents kept in
    //      smem), then in-block hidden izhi; blocks 0..15 add output izhi,
    //      block 16 the loss. No further barriers. ----
    __shared__ float cur[MAXROWS];
    {
        int r0 = range_pt(b, G, HH), r1 = range_pt(b + 1, G, HH);
        int r = r0;
        for (; r + 4 <= r1; r += 4) {
            float a0, a1, a2, a3;
            rows4_dot<ODIM>(Wfb, g_Iout, r, a0, a1, a2, a3);
            block_reduce4(a0, a1, a2, a3);
            if (threadIdx.x == 0) {
                int j = r - r0;
                cur[j + 0] = g_Ihid[r + 0] - a0;
                cur[j + 1] = g_Ihid[r + 1] - a1;
                cur[j + 2] = g_Ihid[r + 2] - a2;
                cur[j + 3] = g_Ihid[r + 3] - a3;
            }
        }
        for (; r < r1; ++r) {
            float a = row1_dot<ODIM>(Wfb, g_Iout, r);
            a = block_reduce1(a);
            if (threadIdx.x == 0)
                cur[r - r0] = g_Ihid[r] - a;
        }
        __syncthreads();

        // Hidden-neuron izhi for this block's own rows (contiguous lanes).
        int nrows = r1 - r0;
        if (threadIdx.x < nrows)
            izhi_run(r0 + threadIdx.x, cur[threadIdx.x], out);
    }

    // Output-neuron izhi: 16 blocks x 256 neurons (needs only g_Iout,
    // finalized at barrier 2).
    if (b < ODIM / 256) {
        int n = b * 256 + threadIdx.x;
        izhi_run(HH + n, g_Iout[n], out);
    } else if (b == ODIM / 256) {
        // loss = mean((I_output - target)^2)
        float acc = 0.0f;
        for (int i = threadIdx.x; i < ODIM; i += 256) {
            float d = g_Iout[i] - target[i];
            acc = fmaf(d, d, acc);
        }
        acc = block_reduce1(acc);
        if (threadIdx.x == 0)
            out[0] = acc / (float)ODIM;
    }
}

extern "C" void kernel_launch(void* const* d_in, const int* in_sizes, int n_in,
                              void* d_out, int out_size) {
    // metadata order: v_input, target_output, W1, W2, W_feedback, gain1, gain2
    const float* v_input = (const float*)d_in[0];
    const float* target  = (const float*)d_in[1];
    const float* W1      = (const float*)d_in[2];
    const float* W2      = (const float*)d_in[3];
    const float* Wfb     = (const float*)d_in[4];
    const float* gain1   = (const float*)d_in[5];
    const float* gain2   = (const float*)d_in[6];
    float* out = (float*)d_out;

    // 4 blocks/SM, guaranteed co-resident (launch_bounds caps regs; take min
    // with the occupancy API for safety — spin barrier must not deadlock).
    int dev = 0;
    cudaGetDevice(&dev);
    int sm = 0;
    cudaDeviceGetAttribute(&sm, cudaDevAttrMultiProcessorCount, dev);
    int occ = 0;
    cudaOccupancyMaxActiveBlocksPerMultiprocessor(&occ, k_fused, 256, 0);
    if (sm < 1) sm = 1;
    int bps = (occ < 4) ? occ : 4;
    if (bps < 1) bps = 1;
    int grid = sm * bps;

    k_fused<<<grid, 256>>>(v_input, target, W1, W2, Wfb, gain1, gain2, out);
    (void)in_sizes; (void)n_in; (void)out_size;
}